// round 2
// baseline (speedup 1.0000x reference)
#include <cuda_runtime.h>
#include <math.h>

// Problem constants (from reference): N=32768, M=8192, D=384, K=9
#define NN 32768
#define MM 8192
#define DD 384
#define KK 9

#define TN 64            // rows per CTA
#define TM 128           // cols per m-tile
#define BK 16            // depth chunk
#define NCHUNK (DD / BK) // 24
#define AS_STRIDE 68     // 64 + pad, 16B-aligned stride (68*4=272)
#define BS_STRIDE 132    // 128 + pad (132*4=528, 16B aligned)
#define CAND_STRIDE 145  // 144 + 1 pad (coprime with 32 banks)

__device__ float g_xnorm[NN];
__device__ float g_ynorm[MM];

// ---------------- row-norm kernels (warp per row) ----------------
__global__ void xnorm_kernel(const float* __restrict__ x) {
    int row = blockIdx.x * blockDim.y + threadIdx.y;
    if (row >= NN) return;
    const float4* xr = (const float4*)(x + (size_t)row * DD);
    float s = 0.f;
    for (int c = threadIdx.x; c < DD / 4; c += 32) {
        float4 v = xr[c];
        s += v.x * v.x + v.y * v.y + v.z * v.z + v.w * v.w;
    }
#pragma unroll
    for (int o = 16; o > 0; o >>= 1) s += __shfl_xor_sync(0xFFFFFFFFu, s, o);
    if (threadIdx.x == 0) g_xnorm[row] = s;
}

__global__ void ynorm_kernel(const float* __restrict__ y) {
    int row = blockIdx.x * blockDim.y + threadIdx.y;
    if (row >= MM) return;
    const float4* yr = (const float4*)(y + (size_t)row * DD);
    float s = 0.f;
    for (int c = threadIdx.x; c < DD / 4; c += 32) {
        float4 v = yr[c];
        s += v.x * v.x + v.y * v.y + v.z * v.z + v.w * v.w;
    }
#pragma unroll
    for (int o = 16; o > 0; o >>= 1) s += __shfl_xor_sync(0xFFFFFFFFu, s, o);
    if (threadIdx.x == 0) g_ynorm[row] = s;
}

// ---------------- fused distance-GEMM + top-9 ----------------
// CTA: 64 rows x full M. A tile persistent in SMEM (transposed),
// B streamed in double-buffered 128x16 chunks. Per-thread top-9 on d2,
// merged per row at the end, then sqrt(max(.,0)).
__global__ __launch_bounds__(256, 1)
void fapm_main(const float* __restrict__ emb, const float* __restrict__ mem,
               float* __restrict__ out) {
    extern __shared__ float smem[];
    float* As   = smem;                       // [DD][AS_STRIDE]  (d-major, transposed A)
    float* Bs   = As + DD * AS_STRIDE;        // [2][BK][BS_STRIDE] (k-major, transposed B)
    float* cand = Bs + 2 * BK * BS_STRIDE;    // [TN][CAND_STRIDE]

    const int tid = threadIdx.x;
    const int tx = tid & 15;    // 0..15 -> 8 cols each
    const int ty = tid >> 4;    // 0..15 -> 4 rows each
    const int row0 = blockIdx.x * TN;

    // ---- stage A (64 x 384) transposed into SMEM ----
    const float4* emb4 = (const float4*)(emb + (size_t)row0 * DD);
    for (int idx = tid; idx < TN * (DD / 4); idx += 256) {
        int r  = idx / (DD / 4);
        int c4 = idx % (DD / 4);
        float4 v = emb4[r * (DD / 4) + c4];
        As[(c4 * 4 + 0) * AS_STRIDE + r] = v.x;
        As[(c4 * 4 + 1) * AS_STRIDE + r] = v.y;
        As[(c4 * 4 + 2) * AS_STRIDE + r] = v.z;
        As[(c4 * 4 + 3) * AS_STRIDE + r] = v.w;
    }
    __syncthreads();

    float xn[4];
#pragma unroll
    for (int i = 0; i < 4; ++i) xn[i] = g_xnorm[row0 + ty * 4 + i];

    // per-thread top-9 (ascending) for each of the 4 owned rows
    float t[4][KK];
#pragma unroll
    for (int i = 0; i < 4; ++i)
#pragma unroll
        for (int j = 0; j < KK; ++j) t[i][j] = 3.4e38f;

    const float4* mem4 = (const float4*)mem;
    const int m_load = tid >> 2;   // 0..63 (this thread's B row, low half)
    const int q_load = tid & 3;    // which float4 within the 16-wide chunk

#pragma unroll 1
    for (int m0 = 0; m0 < MM; m0 += TM) {
        float acc[4][8];
#pragma unroll
        for (int i = 0; i < 4; ++i)
#pragma unroll
            for (int j = 0; j < 8; ++j) acc[i][j] = 0.f;

        float yn[8];
#pragma unroll
        for (int j = 0; j < 8; ++j) yn[j] = g_ynorm[m0 + tx * 8 + j];

        // ---- prologue: stage chunk 0 into buffer 0 ----
        {
            float4 r0 = mem4[(size_t)(m0 + m_load)      * (DD / 4) + q_load];
            float4 r1 = mem4[(size_t)(m0 + m_load + 64) * (DD / 4) + q_load];
            float* b = Bs; // buf 0
            b[(q_load * 4 + 0) * BS_STRIDE + m_load] = r0.x;
            b[(q_load * 4 + 1) * BS_STRIDE + m_load] = r0.y;
            b[(q_load * 4 + 2) * BS_STRIDE + m_load] = r0.z;
            b[(q_load * 4 + 3) * BS_STRIDE + m_load] = r0.w;
            b[(q_load * 4 + 0) * BS_STRIDE + m_load + 64] = r1.x;
            b[(q_load * 4 + 1) * BS_STRIDE + m_load + 64] = r1.y;
            b[(q_load * 4 + 2) * BS_STRIDE + m_load + 64] = r1.z;
            b[(q_load * 4 + 3) * BS_STRIDE + m_load + 64] = r1.w;
        }
        __syncthreads();

#pragma unroll 1
        for (int c = 0; c < NCHUNK; ++c) {
            float4 r0, r1;
            if (c + 1 < NCHUNK) {
                int d4 = (c + 1) * (BK / 4);
                r0 = mem4[(size_t)(m0 + m_load)      * (DD / 4) + d4 + q_load];
                r1 = mem4[(size_t)(m0 + m_load + 64) * (DD / 4) + d4 + q_load];
            }

            // ---- compute this chunk ----
            const float* bbase = Bs + (c & 1) * BK * BS_STRIDE;
            const float* abase = As + c * BK * AS_STRIDE;
#pragma unroll
            for (int k = 0; k < BK; ++k) {
                float4 a  = *(const float4*)(abase + k * AS_STRIDE + ty * 4);
                float4 b0 = *(const float4*)(bbase + k * BS_STRIDE + tx * 8);
                float4 b1 = *(const float4*)(bbase + k * BS_STRIDE + tx * 8 + 4);
                acc[0][0] += a.x * b0.x; acc[0][1] += a.x * b0.y;
                acc[0][2] += a.x * b0.z; acc[0][3] += a.x * b0.w;
                acc[0][4] += a.x * b1.x; acc[0][5] += a.x * b1.y;
                acc[0][6] += a.x * b1.z; acc[0][7] += a.x * b1.w;
                acc[1][0] += a.y * b0.x; acc[1][1] += a.y * b0.y;
                acc[1][2] += a.y * b0.z; acc[1][3] += a.y * b0.w;
                acc[1][4] += a.y * b1.x; acc[1][5] += a.y * b1.y;
                acc[1][6] += a.y * b1.z; acc[1][7] += a.y * b1.w;
                acc[2][0] += a.z * b0.x; acc[2][1] += a.z * b0.y;
                acc[2][2] += a.z * b0.z; acc[2][3] += a.z * b0.w;
                acc[2][4] += a.z * b1.x; acc[2][5] += a.z * b1.y;
                acc[2][6] += a.z * b1.z; acc[2][7] += a.z * b1.w;
                acc[3][0] += a.w * b0.x; acc[3][1] += a.w * b0.y;
                acc[3][2] += a.w * b0.z; acc[3][3] += a.w * b0.w;
                acc[3][4] += a.w * b1.x; acc[3][5] += a.w * b1.y;
                acc[3][6] += a.w * b1.z; acc[3][7] += a.w * b1.w;
            }

            if (c + 1 < NCHUNK) {
                float* b = Bs + ((c + 1) & 1) * BK * BS_STRIDE;
                b[(q_load * 4 + 0) * BS_STRIDE + m_load] = r0.x;
                b[(q_load * 4 + 1) * BS_STRIDE + m_load] = r0.y;
                b[(q_load * 4 + 2) * BS_STRIDE + m_load] = r0.z;
                b[(q_load * 4 + 3) * BS_STRIDE + m_load] = r0.w;
                b[(q_load * 4 + 0) * BS_STRIDE + m_load + 64] = r1.x;
                b[(q_load * 4 + 1) * BS_STRIDE + m_load + 64] = r1.y;
                b[(q_load * 4 + 2) * BS_STRIDE + m_load + 64] = r1.z;
                b[(q_load * 4 + 3) * BS_STRIDE + m_load + 64] = r1.w;
            }
            __syncthreads();
        }

        // ---- fold this tile into per-thread top-9 (on d2) ----
#pragma unroll
        for (int i = 0; i < 4; ++i) {
#pragma unroll
            for (int j = 0; j < 8; ++j) {
                float v = xn[i] + yn[j] - 2.f * acc[i][j];
                if (v < t[i][KK - 1]) {
                    // branchless sorted insert (ascending)
#pragma unroll
                    for (int p = KK - 1; p > 0; --p)
                        t[i][p] = (v < t[i][p - 1]) ? t[i][p - 1] : fminf(v, t[i][p]);
                    t[i][0] = fminf(t[i][0], v);
                }
            }
        }
    }

    // ---- merge 16 per-thread lists per row ----
    __syncthreads();
#pragma unroll
    for (int i = 0; i < 4; ++i)
#pragma unroll
        for (int j = 0; j < KK; ++j)
            cand[(ty * 4 + i) * CAND_STRIDE + tx * KK + j] = t[i][j];
    __syncthreads();

    if (tid < TN) {
        float* c = &cand[tid * CAND_STRIDE];
        const int NC = 16 * KK; // 144 candidates
        float* o = out + (size_t)(row0 + tid) * KK;
#pragma unroll 1
        for (int k = 0; k < KK; ++k) {
            float mv = c[k];
            int mi = k;
            for (int j = k + 1; j < NC; ++j) {
                float v = c[j];
                if (v < mv) { mv = v; mi = j; }
            }
            c[mi] = c[k];
            c[k] = mv;
            o[k] = sqrtf(fmaxf(mv, 0.f));
        }
    }
}

extern "C" void kernel_launch(void* const* d_in, const int* in_sizes, int n_in,
                              void* d_out, int out_size) {
    const float* emb = (const float*)d_in[0];   // [N, D] fp32
    const float* mem = (const float*)d_in[1];   // [M, D] fp32
    float* out = (float*)d_out;                 // [N, K] fp32

    // norms
    dim3 nb(32, 8);
    xnorm_kernel<<<NN / 8, nb>>>(emb);
    ynorm_kernel<<<MM / 8, nb>>>(mem);

    // fused distance GEMM + top-9
    const int smem_bytes = (DD * AS_STRIDE + 2 * BK * BS_STRIDE + TN * CAND_STRIDE) * (int)sizeof(float);
    cudaFuncSetAttribute(fapm_main, cudaFuncAttributeMaxDynamicSharedMemorySize, smem_bytes);
    fapm_main<<<NN / TN, 256, smem_bytes>>>(emb, mem, out);
}

// round 4
// speedup vs baseline: 7.2978x; 7.2978x over previous
#include <cuda_runtime.h>
#include <cuda_bf16.h>
#include <math.h>

// Problem constants: N=32768, M=8192, D=384, K=9
#define NN 32768
#define MM 8192
#define DD 384
#define KK 9

#define BM 128                 // embedding rows per CTA
#define BN 128                 // bank cols per tile
#define BK 64                  // k per chunk
#define NKC (DD / BK)          // 6
#define NMIT (MM / BN)         // 64

#define A_STRIDE_BF 392        // 384 + 8 pad (392*2=784 B; 196 words ≡ 4 mod 32)
#define A_ROW_BYTES (A_STRIDE_BF * 2)
#define A_BYTES (BM * A_ROW_BYTES)          // 100352
#define B_STRIDE_BF 72         // 64 + 8 pad (144 B; 36 words ≡ 4 mod 32)
#define B_ROW_BYTES (B_STRIDE_BF * 2)
#define B_BUF_BYTES (BN * B_ROW_BYTES)      // 18432
#define CAND_STRIDE 37

#define OFF_B   A_BYTES
#define OFF_YN  (OFF_B + 2 * B_BUF_BYTES)
#define OFF_CAND (OFF_YN + BN * 4)
#define SMEM_BYTES (OFF_CAND + BM * CAND_STRIDE * 4)

__device__ __nv_bfloat16 g_Abf[(size_t)NN * DD];
__device__ __nv_bfloat16 g_Bbf[(size_t)MM * DD];
__device__ float g_xnorm[NN];
__device__ float g_ynorm[MM];

// ---------------- helpers ----------------
__device__ __forceinline__ unsigned smem_u32(const void* p) {
    unsigned a;
    asm("{ .reg .u64 t; cvta.to.shared.u64 t, %1; cvt.u32.u64 %0, t; }" : "=r"(a) : "l"(p));
    return a;
}
#define CP_ASYNC16(dst, src) asm volatile("cp.async.cg.shared.global [%0], [%1], 16;" :: "r"(dst), "l"(src) : "memory")
#define CP_COMMIT()  asm volatile("cp.async.commit_group;" ::: "memory")
#define CP_WAIT0()   asm volatile("cp.async.wait_group 0;" ::: "memory")
#define CP_WAIT1()   asm volatile("cp.async.wait_group 1;" ::: "memory")

#define LDSM4(r, addr) \
    asm volatile("ldmatrix.sync.aligned.m8n8.x4.shared.b16 {%0,%1,%2,%3}, [%4];" \
        : "=r"((r)[0]), "=r"((r)[1]), "=r"((r)[2]), "=r"((r)[3]) : "r"(addr))

#define MMA_16816(d, a, b0, b1) \
    asm volatile("mma.sync.aligned.m16n8k16.row.col.f32.bf16.bf16.f32 " \
        "{%0,%1,%2,%3}, {%4,%5,%6,%7}, {%8,%9}, {%0,%1,%2,%3};" \
        : "+f"((d)[0]), "+f"((d)[1]), "+f"((d)[2]), "+f"((d)[3]) \
        : "r"((a)[0]), "r"((a)[1]), "r"((a)[2]), "r"((a)[3]), "r"(b0), "r"(b1))

// ---------------- convert + norm pre-pass ----------------
__device__ __forceinline__ void conv_row(const float* __restrict__ src,
                                         __nv_bfloat16* __restrict__ dst,
                                         float* __restrict__ norm, int row) {
    const float4* s4 = (const float4*)(src + (size_t)row * DD);
    __nv_bfloat162* d2p = (__nv_bfloat162*)(dst + (size_t)row * DD);
    float s = 0.f;
    for (int c = threadIdx.x; c < DD / 4; c += 32) {
        float4 v = s4[c];
        s += v.x * v.x + v.y * v.y + v.z * v.z + v.w * v.w;
        d2p[c * 2 + 0] = __floats2bfloat162_rn(v.x, v.y);
        d2p[c * 2 + 1] = __floats2bfloat162_rn(v.z, v.w);
    }
#pragma unroll
    for (int o = 16; o > 0; o >>= 1) s += __shfl_xor_sync(0xFFFFFFFFu, s, o);
    if (threadIdx.x == 0) norm[row] = s;
}
__global__ void conv_x(const float* __restrict__ src) {
    conv_row(src, g_Abf, g_xnorm, blockIdx.x * 8 + threadIdx.y);
}
__global__ void conv_y(const float* __restrict__ src) {
    conv_row(src, g_Bbf, g_ynorm, blockIdx.x * 8 + threadIdx.y);
}

__device__ __forceinline__ void top9_insert(float* t, float v) {
    if (v < t[KK - 1]) {
#pragma unroll
        for (int p = KK - 1; p > 0; --p)
            t[p] = (v < t[p - 1]) ? t[p - 1] : fminf(v, t[p]);
        t[0] = fminf(t[0], v);
    }
}

// ---------------- main fused kernel ----------------
__global__ void __launch_bounds__(256, 1) fapm_mma(float* __restrict__ out) {
    extern __shared__ char smem[];
    float* ynS  = (float*)(smem + OFF_YN);
    float* cand = (float*)(smem + OFF_CAND);

    const int tid = threadIdx.x;
    const int l = tid & 31;
    const int w = tid >> 5;
    const int row0 = blockIdx.x * BM;

    const unsigned Abase = smem_u32(smem);
    const unsigned Bbase = Abase + OFF_B;

    // ---- stage A (128 x 384 bf16) into padded SMEM ----
    {
        const __nv_bfloat16* Ag = g_Abf + (size_t)row0 * DD;
#pragma unroll
        for (int i = 0; i < 24; ++i) {
            int idx = tid + i * 256;
            int r = idx / 48, sl = idx % 48;
            CP_ASYNC16(Abase + r * A_ROW_BYTES + sl * 16,
                       (const void*)(Ag + (size_t)r * DD + sl * 8));
        }
        CP_COMMIT();
    }

    const float xn_lo = g_xnorm[row0 + w * 16 + (l >> 2)];
    const float xn_hi = g_xnorm[row0 + w * 16 + (l >> 2) + 8];

    // per-lane ldmatrix offsets
    const unsigned a_off = Abase + (w * 16 + (l & 15)) * A_ROW_BYTES + ((l & 16) ? 16 : 0);
    const unsigned b_off = ((l & 7) + ((l & 16) ? 8 : 0)) * B_ROW_BYTES + ((l & 8) ? 16 : 0);

    float tk[2][KK];
#pragma unroll
    for (int j = 0; j < KK; ++j) { tk[0][j] = 3.4e38f; tk[1][j] = 3.4e38f; }

    CP_WAIT0();
    __syncthreads();

#pragma unroll 1
    for (int mi = 0; mi < NMIT; ++mi) {
        const int m0 = mi * BN;
        float acc[64];
#pragma unroll
        for (int i = 0; i < 64; ++i) acc[i] = 0.f;

        // issue chunk 0 -> buf 0
        {
            const __nv_bfloat16* Bg = g_Bbf + (size_t)m0 * DD;
#pragma unroll
            for (int i = 0; i < 4; ++i) {
                int idx = tid + i * 256;
                int n = idx >> 3, k8 = idx & 7;
                CP_ASYNC16(Bbase + n * B_ROW_BYTES + k8 * 16,
                           (const void*)(Bg + (size_t)n * DD + k8 * 8));
            }
            CP_COMMIT();
        }
        if (tid < BN) ynS[tid] = g_ynorm[m0 + tid];

#pragma unroll 1
        for (int c = 0; c < NKC; ++c) {
            if (c + 1 < NKC) {
                const __nv_bfloat16* Bg = g_Bbf + (size_t)m0 * DD + (c + 1) * BK;
                unsigned dstb = Bbase + ((c + 1) & 1) * B_BUF_BYTES;
#pragma unroll
                for (int i = 0; i < 4; ++i) {
                    int idx = tid + i * 256;
                    int n = idx >> 3, k8 = idx & 7;
                    CP_ASYNC16(dstb + n * B_ROW_BYTES + k8 * 16,
                               (const void*)(Bg + (size_t)n * DD + k8 * 8));
                }
                CP_COMMIT();
                CP_WAIT1();
            } else {
                CP_WAIT0();
            }
            __syncthreads();

            const unsigned bbuf = Bbase + (c & 1) * B_BUF_BYTES + b_off;
            const unsigned abuf = a_off + c * 128;
#pragma unroll
            for (int ks = 0; ks < 4; ++ks) {
                unsigned a[4];
                LDSM4(a, abuf + ks * 32);
                unsigned bf[32];
#pragma unroll
                for (int i = 0; i < 8; ++i)
                    LDSM4(&bf[i * 4], bbuf + i * 2304 + ks * 32);
#pragma unroll
                for (int nt = 0; nt < 16; ++nt)
                    MMA_16816(acc + nt * 4, a, bf[nt * 2], bf[nt * 2 + 1]);
            }
            __syncthreads();
        }

        // ---- epilogue: fold tile into per-thread top-9 ----
#pragma unroll
        for (int nt = 0; nt < 16; ++nt) {
            float yn0 = ynS[nt * 8 + (l & 3) * 2];
            float yn1 = ynS[nt * 8 + (l & 3) * 2 + 1];
            top9_insert(tk[0], fmaf(-2.f, acc[nt * 4 + 0], xn_lo + yn0));
            top9_insert(tk[0], fmaf(-2.f, acc[nt * 4 + 1], xn_lo + yn1));
            top9_insert(tk[1], fmaf(-2.f, acc[nt * 4 + 2], xn_hi + yn0));
            top9_insert(tk[1], fmaf(-2.f, acc[nt * 4 + 3], xn_hi + yn1));
        }
        __syncthreads();   // ynS / B-buf reuse barrier
    }

    // ---- merge 4 per-thread lists per row ----
    const int r_lo = w * 16 + (l >> 2);
#pragma unroll
    for (int j = 0; j < KK; ++j) {
        cand[r_lo * CAND_STRIDE + (l & 3) * KK + j] = tk[0][j];
        cand[(r_lo + 8) * CAND_STRIDE + (l & 3) * KK + j] = tk[1][j];
    }
    __syncthreads();

    if (tid < BM) {
        float* c = &cand[tid * CAND_STRIDE];
        float* o = out + (size_t)(row0 + tid) * KK;
        const int NC = 4 * KK;
#pragma unroll 1
        for (int k = 0; k < KK; ++k) {
            float mv = c[k];
            int mi2 = k;
            for (int j = k + 1; j < NC; ++j) {
                float v = c[j];
                if (v < mv) { mv = v; mi2 = j; }
            }
            c[mi2] = c[k];
            c[k] = mv;
            o[k] = sqrtf(fmaxf(mv, 0.f));
        }
    }
}

extern "C" void kernel_launch(void* const* d_in, const int* in_sizes, int n_in,
                              void* d_out, int out_size) {
    const float* emb = (const float*)d_in[0];   // [N, D] fp32
    const float* mem = (const float*)d_in[1];   // [M, D] fp32
    float* out = (float*)d_out;                 // [N, K] fp32

    dim3 cb(32, 8);
    conv_x<<<NN / 8, cb>>>(emb);
    conv_y<<<MM / 8, cb>>>(mem);

    cudaFuncSetAttribute(fapm_mma, cudaFuncAttributeMaxDynamicSharedMemorySize, SMEM_BYTES);
    fapm_mma<<<NN / BM, 256, SMEM_BYTES>>>(out);
}

// round 6
// speedup vs baseline: 7.4757x; 1.0244x over previous
#include <cuda_runtime.h>
#include <cuda_bf16.h>
#include <math.h>

// Problem constants: N=32768, M=8192, D=384, K=9
#define NN 32768
#define MM 8192
#define DD 384
#define KK 9

#define BM 128                 // embedding rows per CTA
#define BN 128                 // bank cols per tile
#define BK 64                  // k per chunk
#define NKC (DD / BK)          // 6
#define NMIT (MM / BN)         // 64
#define NCHUNKS (NMIT * NKC)   // 384
#define NB 3                   // B buffers

#define A_STRIDE_BF 392        // 384+8 pad; 196 words ≡ 4 mod 32 -> conflict-free ldmatrix
#define A_ROW_BYTES (A_STRIDE_BF * 2)
#define A_BYTES (BM * A_ROW_BYTES)          // 100352
#define B_STRIDE_BF 72         // 64+8 pad; 36 words ≡ 4 mod 32
#define B_ROW_BYTES (B_STRIDE_BF * 2)       // 144
#define B_BUF_BYTES (BN * B_ROW_BYTES)      // 18432
#define CAND_STRIDE 73         // 8 lists * 9 + 1

#define OFF_B   A_BYTES                          // 100352
#define OFF_YN  (OFF_B + NB * B_BUF_BYTES)       // 155648
#define OFF_CAND (OFF_YN + 2 * BN * 4)           // 156672
#define SMEM_BYTES (OFF_CAND + BM * CAND_STRIDE * 4)  // 194048

__device__ __nv_bfloat16 g_Abf[(size_t)NN * DD];
__device__ __nv_bfloat16 g_Bbf[(size_t)MM * DD];
__device__ float g_xnorm[NN];
__device__ float g_ynorm[MM];

// ---------------- helpers ----------------
__device__ __forceinline__ unsigned smem_u32(const void* p) {
    unsigned a;
    asm("{ .reg .u64 t; cvta.to.shared.u64 t, %1; cvt.u32.u64 %0, t; }" : "=r"(a) : "l"(p));
    return a;
}
#define CP_ASYNC16(dst, src) asm volatile("cp.async.cg.shared.global [%0], [%1], 16;" :: "r"(dst), "l"(src) : "memory")
#define CP_COMMIT()  asm volatile("cp.async.commit_group;" ::: "memory")
#define CP_WAIT0()   asm volatile("cp.async.wait_group 0;" ::: "memory")
#define CP_WAIT1()   asm volatile("cp.async.wait_group 1;" ::: "memory")

#define LDSM4(r, addr) \
    asm volatile("ldmatrix.sync.aligned.m8n8.x4.shared.b16 {%0,%1,%2,%3}, [%4];" \
        : "=r"((r)[0]), "=r"((r)[1]), "=r"((r)[2]), "=r"((r)[3]) : "r"(addr))

#define MMA_16816(d, a, b0, b1) \
    asm volatile("mma.sync.aligned.m16n8k16.row.col.f32.bf16.bf16.f32 " \
        "{%0,%1,%2,%3}, {%4,%5,%6,%7}, {%8,%9}, {%0,%1,%2,%3};" \
        : "+f"((d)[0]), "+f"((d)[1]), "+f"((d)[2]), "+f"((d)[3]) \
        : "r"((a)[0]), "r"((a)[1]), "r"((a)[2]), "r"((a)[3]), "r"(b0), "r"(b1))

// ---------------- merged convert + norm pre-pass ----------------
__global__ void conv_all(const float* __restrict__ x, const float* __restrict__ y) {
    int bid = blockIdx.x;
    const float* src;
    __nv_bfloat16* dst;
    float* norm;
    int row;
    if (bid < NN / 8) {
        row = bid * 8 + threadIdx.y;
        src = x; dst = g_Abf; norm = g_xnorm;
    } else {
        row = (bid - NN / 8) * 8 + threadIdx.y;
        src = y; dst = g_Bbf; norm = g_ynorm;
    }
    const float4* s4 = (const float4*)(src + (size_t)row * DD);
    __nv_bfloat162* d2p = (__nv_bfloat162*)(dst + (size_t)row * DD);
    float s = 0.f;
    for (int c = threadIdx.x; c < DD / 4; c += 32) {
        float4 v = s4[c];
        s += v.x * v.x + v.y * v.y + v.z * v.z + v.w * v.w;
        d2p[c * 2 + 0] = __floats2bfloat162_rn(v.x, v.y);
        d2p[c * 2 + 1] = __floats2bfloat162_rn(v.z, v.w);
    }
#pragma unroll
    for (int o = 16; o > 0; o >>= 1) s += __shfl_xor_sync(0xFFFFFFFFu, s, o);
    if (threadIdx.x == 0) norm[row] = s;
}

__device__ __forceinline__ void top9_insert(float* t, float v) {
    if (v < t[KK - 1]) {
#pragma unroll
        for (int p = KK - 1; p > 0; --p)
            t[p] = (v < t[p - 1]) ? t[p - 1] : fminf(v, t[p]);
        t[0] = fminf(t[0], v);
    }
}

// ---------------- main fused kernel ----------------
// 512 threads = 16 warps = 8 (M) x 2 (N). Warp tile: 16 rows x 64 cols.
// B streamed in 3 buffers, one __syncthreads per 64-k chunk, 384-chunk stream.
__global__ void __launch_bounds__(512, 1) fapm_mma(float* __restrict__ out) {
    extern __shared__ char smem[];
    float* ynS  = (float*)(smem + OFF_YN);
    float* cand = (float*)(smem + OFF_CAND);

    const int tid = threadIdx.x;
    const int l = tid & 31;
    const int w = tid >> 5;
    const int wm = w >> 1;     // 0..7 : M position
    const int wn = w & 1;      // 0..1 : N position
    const int row0 = blockIdx.x * BM;

    const unsigned Abase = smem_u32(smem);
    const unsigned Bbase = Abase + OFF_B;

    // ---- group 0: stage A (128 x 384 bf16) ----
    {
        const __nv_bfloat16* Ag = g_Abf + (size_t)row0 * DD;
#pragma unroll
        for (int i = 0; i < 12; ++i) {
            int idx = tid + i * 512;
            int r = idx / 48, sl = idx % 48;
            CP_ASYNC16(Abase + r * A_ROW_BYTES + sl * 16,
                       (const void*)(Ag + (size_t)r * DD + sl * 8));
        }
        CP_COMMIT();
    }
    // ---- groups 1,2: B chunks 0,1 ----
#pragma unroll
    for (int ck = 0; ck < 2; ++ck) {
        const __nv_bfloat16* Bg = g_Bbf + ck * BK;   // tile 0, chunk ck
        unsigned dstb = Bbase + ck * B_BUF_BYTES;
#pragma unroll
        for (int i = 0; i < 2; ++i) {
            int idx = tid + i * 512;
            int n = idx >> 3, k8 = idx & 7;
            CP_ASYNC16(dstb + n * B_ROW_BYTES + k8 * 16,
                       (const void*)(Bg + (size_t)n * DD + k8 * 8));
        }
        CP_COMMIT();
    }

    const float xn_lo = g_xnorm[row0 + wm * 16 + (l >> 2)];
    const float xn_hi = g_xnorm[row0 + wm * 16 + (l >> 2) + 8];

    // per-lane ldmatrix base offsets
    const unsigned a_off = Abase + (wm * 16 + (l & 15)) * A_ROW_BYTES + ((l & 16) ? 16 : 0);
    const unsigned b_lane = ((l & 7) + ((l & 16) ? 8 : 0)) * B_ROW_BYTES + ((l & 8) ? 16 : 0)
                            + wn * 64 * B_ROW_BYTES;

    float tk[2][KK];
#pragma unroll
    for (int j = 0; j < KK; ++j) { tk[0][j] = 3.4e38f; tk[1][j] = 3.4e38f; }

    float acc[32];
#pragma unroll
    for (int i = 0; i < 32; ++i) acc[i] = 0.f;

    // chunk-stream counters
    int c6 = 0, mi = 0, b3 = 0;          // current chunk: phase-in-tile, tile, buffer
    int is_c = 2, is_mi = 0, is_b3 = 2;  // issue cursor (chunk cc+2)

#pragma unroll 1
    for (int cc = 0; cc < NCHUNKS; ++cc) {
        if (cc >= NCHUNKS - 2) { CP_WAIT0(); } else { CP_WAIT1(); }
        __syncthreads();

        if (c6 == 0 && tid < BN)
            ynS[(mi & 1) * BN + tid] = g_ynorm[mi * BN + tid];

        // issue chunk cc+2
        if (cc + 2 < NCHUNKS) {
            const __nv_bfloat16* Bg = g_Bbf + (size_t)(is_mi * BN) * DD + is_c * BK;
            unsigned dstb = Bbase + is_b3 * B_BUF_BYTES;
#pragma unroll
            for (int i = 0; i < 2; ++i) {
                int idx = tid + i * 512;
                int n = idx >> 3, k8 = idx & 7;
                CP_ASYNC16(dstb + n * B_ROW_BYTES + k8 * 16,
                           (const void*)(Bg + (size_t)n * DD + k8 * 8));
            }
            CP_COMMIT();
            if (++is_c == NKC) { is_c = 0; ++is_mi; }
            if (++is_b3 == NB) is_b3 = 0;
        }

        // compute chunk cc
        {
            const unsigned bbuf = Bbase + b3 * B_BUF_BYTES + b_lane;
            const unsigned abuf = a_off + c6 * 128;
#pragma unroll
            for (int ks = 0; ks < 4; ++ks) {
                unsigned a[4];
                LDSM4(a, abuf + ks * 32);
                unsigned bf[16];
#pragma unroll
                for (int i = 0; i < 4; ++i)
                    LDSM4(&bf[i * 4], bbuf + i * 16 * B_ROW_BYTES + ks * 32);
#pragma unroll
                for (int nt = 0; nt < 8; ++nt)
                    MMA_16816(acc + nt * 4, a, bf[nt * 2], bf[nt * 2 + 1]);
            }
        }

        // epilogue at end of tile
        if (c6 == 5) {
            const float* yn = &ynS[(mi & 1) * BN + wn * 64 + (l & 3) * 2];
#pragma unroll
            for (int nt = 0; nt < 8; ++nt) {
                float yn0 = yn[nt * 8];
                float yn1 = yn[nt * 8 + 1];
                top9_insert(tk[0], fmaf(-2.f, acc[nt * 4 + 0], xn_lo + yn0));
                top9_insert(tk[0], fmaf(-2.f, acc[nt * 4 + 1], xn_lo + yn1));
                top9_insert(tk[1], fmaf(-2.f, acc[nt * 4 + 2], xn_hi + yn0));
                top9_insert(tk[1], fmaf(-2.f, acc[nt * 4 + 3], xn_hi + yn1));
            }
#pragma unroll
            for (int i = 0; i < 32; ++i) acc[i] = 0.f;
        }

        if (++c6 == NKC) { c6 = 0; ++mi; }
        if (++b3 == NB) b3 = 0;
    }

    // ---- merge 8 per-thread lists per row ----
    const int r_lo = wm * 16 + (l >> 2);
    const int lst = wn * 4 + (l & 3);
#pragma unroll
    for (int j = 0; j < KK; ++j) {
        cand[r_lo * CAND_STRIDE + lst * KK + j] = tk[0][j];
        cand[(r_lo + 8) * CAND_STRIDE + lst * KK + j] = tk[1][j];
    }
    __syncthreads();

    if (tid < BM) {
        float* c = &cand[tid * CAND_STRIDE];
        float* o = out + (size_t)(row0 + tid) * KK;
        const int NC = 8 * KK;
#pragma unroll 1
        for (int k = 0; k < KK; ++k) {
            float mv = c[k];
            int mi2 = k;
            for (int j = k + 1; j < NC; ++j) {
                float v = c[j];
                if (v < mv) { mv = v; mi2 = j; }
            }
            c[mi2] = c[k];
            c[k] = mv;
            o[k] = sqrtf(fmaxf(mv, 0.f));
        }
    }
}

extern "C" void kernel_launch(void* const* d_in, const int* in_sizes, int n_in,
                              void* d_out, int out_size) {
    const float* emb = (const float*)d_in[0];   // [N, D] fp32
    const float* mem = (const float*)d_in[1];   // [M, D] fp32
    float* out = (float*)d_out;                 // [N, K] fp32

    dim3 cb(32, 8);
    conv_all<<<NN / 8 + MM / 8, cb>>>(emb, mem);

    cudaFuncSetAttribute(fapm_mma, cudaFuncAttributeMaxDynamicSharedMemorySize, SMEM_BYTES);
    fapm_mma<<<NN / BM, 512, SMEM_BYTES>>>(out);
}

// round 7
// speedup vs baseline: 8.2065x; 1.0978x over previous
#include <cuda_runtime.h>
#include <cuda_bf16.h>
#include <math.h>

// Problem constants: N=32768, M=8192, D=384, K=9
#define NN 32768
#define MM 8192
#define DD 384
#define KK 9

#define BM 128                 // embedding rows per CTA
#define BN 256                 // bank cols per tile
#define BK 64                  // k per chunk
#define NKC (DD / BK)          // 6
#define NMIT (MM / BN)         // 32
#define NCHUNKS (NMIT * NKC)   // 192
#define NB 3                   // B buffers

#define A_STRIDE_BF 392        // 384+8 pad; 196 words ≡ 4 mod 32 -> conflict-free ldmatrix
#define A_ROW_BYTES (A_STRIDE_BF * 2)       // 784
#define A_BYTES (BM * A_ROW_BYTES)          // 100352
#define B_STRIDE_BF 72         // 64+8 pad; 36 words ≡ 4 mod 32
#define B_ROW_BYTES (B_STRIDE_BF * 2)       // 144
#define B_BUF_BYTES (BN * B_ROW_BYTES)      // 36864
#define CAND_STRIDE 145        // 16 lists * 9 + 1

#define OFF_B   A_BYTES                          // 100352
#define OFF_YN  (OFF_B + NB * B_BUF_BYTES)       // 210944
#define SMEM_BYTES (OFF_YN + 2 * BN * 4)         // 212992
// cand (128*145*4 = 74240 B) overlays the B buffers after the main loop

__device__ __nv_bfloat16 g_Abf[(size_t)NN * DD];
__device__ __nv_bfloat16 g_Bbf[(size_t)MM * DD];
__device__ float g_xnorm[NN];
__device__ float g_ynorm[MM];

// ---------------- helpers ----------------
__device__ __forceinline__ unsigned smem_u32(const void* p) {
    unsigned a;
    asm("{ .reg .u64 t; cvta.to.shared.u64 t, %1; cvt.u32.u64 %0, t; }" : "=r"(a) : "l"(p));
    return a;
}
#define CP_ASYNC16(dst, src) asm volatile("cp.async.cg.shared.global [%0], [%1], 16;" :: "r"(dst), "l"(src) : "memory")
#define CP_COMMIT()  asm volatile("cp.async.commit_group;" ::: "memory")
#define CP_WAIT0()   asm volatile("cp.async.wait_group 0;" ::: "memory")
#define CP_WAIT1()   asm volatile("cp.async.wait_group 1;" ::: "memory")

#define LDSM4(r, addr) \
    asm volatile("ldmatrix.sync.aligned.m8n8.x4.shared.b16 {%0,%1,%2,%3}, [%4];" \
        : "=r"((r)[0]), "=r"((r)[1]), "=r"((r)[2]), "=r"((r)[3]) : "r"(addr))

#define MMA_16816(d, a, b0, b1) \
    asm volatile("mma.sync.aligned.m16n8k16.row.col.f32.bf16.bf16.f32 " \
        "{%0,%1,%2,%3}, {%4,%5,%6,%7}, {%8,%9}, {%0,%1,%2,%3};" \
        : "+f"((d)[0]), "+f"((d)[1]), "+f"((d)[2]), "+f"((d)[3]) \
        : "r"((a)[0]), "r"((a)[1]), "r"((a)[2]), "r"((a)[3]), "r"(b0), "r"(b1))

// ---------------- merged convert + norm pre-pass ----------------
__global__ void conv_all(const float* __restrict__ x, const float* __restrict__ y) {
    int bid = blockIdx.x;
    const float* src;
    __nv_bfloat16* dst;
    float* norm;
    int row;
    if (bid < NN / 8) {
        row = bid * 8 + threadIdx.y;
        src = x; dst = g_Abf; norm = g_xnorm;
    } else {
        row = (bid - NN / 8) * 8 + threadIdx.y;
        src = y; dst = g_Bbf; norm = g_ynorm;
    }
    const float4* s4 = (const float4*)(src + (size_t)row * DD);
    __nv_bfloat162* d2p = (__nv_bfloat162*)(dst + (size_t)row * DD);
    float s = 0.f;
    for (int c = threadIdx.x; c < DD / 4; c += 32) {
        float4 v = s4[c];
        s += v.x * v.x + v.y * v.y + v.z * v.z + v.w * v.w;
        d2p[c * 2 + 0] = __floats2bfloat162_rn(v.x, v.y);
        d2p[c * 2 + 1] = __floats2bfloat162_rn(v.z, v.w);
    }
#pragma unroll
    for (int o = 16; o > 0; o >>= 1) s += __shfl_xor_sync(0xFFFFFFFFu, s, o);
    if (threadIdx.x == 0) norm[row] = s;
}

__device__ __forceinline__ void top9_insert(float* t, float v) {
    if (v < t[KK - 1]) {
#pragma unroll
        for (int p = KK - 1; p > 0; --p)
            t[p] = (v < t[p - 1]) ? t[p - 1] : fminf(v, t[p]);
        t[0] = fminf(t[0], v);
    }
}

// ---------------- main fused kernel ----------------
// 512 threads = 16 warps = 4 (M) x 4 (N). Warp tile: 32 rows x 64 cols.
// Per k-step per warp: 2 A + 4 B ldmatrix.x4 feed 16 HMMA (2 m-groups x 8 n-groups).
__global__ void __launch_bounds__(512, 1) fapm_mma(float* __restrict__ out) {
    extern __shared__ char smem[];
    float* ynS  = (float*)(smem + OFF_YN);
    float* cand = (float*)(smem + OFF_B);   // overlay, used after main loop

    const int tid = threadIdx.x;
    const int l = tid & 31;
    const int w = tid >> 5;
    const int wm = w & 3;      // 0..3 : M position (32 rows each)
    const int wn = w >> 2;     // 0..3 : N position (64 cols each)
    const int row0 = blockIdx.x * BM;

    const unsigned Abase = smem_u32(smem);
    const unsigned Bbase = Abase + OFF_B;

    // ---- group 0: stage A (128 x 384 bf16) ----
    {
        const __nv_bfloat16* Ag = g_Abf + (size_t)row0 * DD;
#pragma unroll
        for (int i = 0; i < 12; ++i) {
            int idx = tid + i * 512;
            int r = idx / 48, sl = idx % 48;
            CP_ASYNC16(Abase + r * A_ROW_BYTES + sl * 16,
                       (const void*)(Ag + (size_t)r * DD + sl * 8));
        }
        CP_COMMIT();
    }
    // ---- groups 1,2: B chunks 0,1 (tile 0) ----
#pragma unroll
    for (int ck = 0; ck < 2; ++ck) {
        const __nv_bfloat16* Bg = g_Bbf + ck * BK;
        unsigned dstb = Bbase + ck * B_BUF_BYTES;
#pragma unroll
        for (int i = 0; i < 4; ++i) {
            int idx = tid + i * 512;
            int n = idx >> 3, k8 = idx & 7;
            CP_ASYNC16(dstb + n * B_ROW_BYTES + k8 * 16,
                       (const void*)(Bg + (size_t)n * DD + k8 * 8));
        }
        CP_COMMIT();
    }

    // 4 global rows per thread: wm*32 + (l>>2) + {0,8,16,24}
    float xn[4];
#pragma unroll
    for (int g = 0; g < 4; ++g) xn[g] = g_xnorm[row0 + wm * 32 + (l >> 2) + g * 8];

    // per-lane ldmatrix base offsets
    const unsigned a_off = Abase + (wm * 32 + (l & 15)) * A_ROW_BYTES + ((l & 16) ? 16 : 0);
    const unsigned b_lane = ((l & 7) + ((l & 16) ? 8 : 0)) * B_ROW_BYTES + ((l & 8) ? 16 : 0)
                            + wn * 64 * B_ROW_BYTES;

    float tk[4][KK];
#pragma unroll
    for (int g = 0; g < 4; ++g)
#pragma unroll
        for (int j = 0; j < KK; ++j) tk[g][j] = 3.4e38f;

    float acc[64];
#pragma unroll
    for (int i = 0; i < 64; ++i) acc[i] = 0.f;

    // chunk-stream counters
    int c6 = 0, mi = 0, b3 = 0;          // current chunk: phase-in-tile, tile, buffer
    int is_c = 2, is_mi = 0, is_b3 = 2;  // issue cursor (chunk cc+2)

#pragma unroll 1
    for (int cc = 0; cc < NCHUNKS; ++cc) {
        if (cc >= NCHUNKS - 2) { CP_WAIT0(); } else { CP_WAIT1(); }
        __syncthreads();

        if (c6 == 0 && tid < BN)
            ynS[(mi & 1) * BN + tid] = g_ynorm[mi * BN + tid];

        // issue chunk cc+2
        if (cc + 2 < NCHUNKS) {
            const __nv_bfloat16* Bg = g_Bbf + (size_t)(is_mi * BN) * DD + is_c * BK;
            unsigned dstb = Bbase + is_b3 * B_BUF_BYTES;
#pragma unroll
            for (int i = 0; i < 4; ++i) {
                int idx = tid + i * 512;
                int n = idx >> 3, k8 = idx & 7;
                CP_ASYNC16(dstb + n * B_ROW_BYTES + k8 * 16,
                           (const void*)(Bg + (size_t)n * DD + k8 * 8));
            }
            CP_COMMIT();
            if (++is_c == NKC) { is_c = 0; ++is_mi; }
            if (++is_b3 == NB) is_b3 = 0;
        }

        // compute chunk cc: 4 k-steps of k16
        {
            const unsigned bbuf = Bbase + b3 * B_BUF_BYTES + b_lane;
            const unsigned abuf = a_off + c6 * 128;
#pragma unroll
            for (int ks = 0; ks < 4; ++ks) {
                unsigned a0[4], a1[4];
                LDSM4(a0, abuf + ks * 32);
                LDSM4(a1, abuf + 16 * A_ROW_BYTES + ks * 32);
#pragma unroll
                for (int i = 0; i < 4; ++i) {
                    unsigned bf[4];
                    LDSM4(bf, bbuf + i * 16 * B_ROW_BYTES + ks * 32);
                    MMA_16816(acc + (i * 2 + 0) * 4,      a0, bf[0], bf[1]);
                    MMA_16816(acc + (i * 2 + 1) * 4,      a0, bf[2], bf[3]);
                    MMA_16816(acc + 32 + (i * 2 + 0) * 4, a1, bf[0], bf[1]);
                    MMA_16816(acc + 32 + (i * 2 + 1) * 4, a1, bf[2], bf[3]);
                }
            }
        }

        // epilogue at end of tile
        if (c6 == 5) {
            const float* yn = &ynS[(mi & 1) * BN + wn * 64 + (l & 3) * 2];
#pragma unroll
            for (int mg = 0; mg < 2; ++mg) {
#pragma unroll
                for (int nt = 0; nt < 8; ++nt) {
                    float yn0 = yn[nt * 8];
                    float yn1 = yn[nt * 8 + 1];
                    float* ac = acc + mg * 32 + nt * 4;
                    top9_insert(tk[mg * 2 + 0], fmaf(-2.f, ac[0], xn[mg * 2 + 0] + yn0));
                    top9_insert(tk[mg * 2 + 0], fmaf(-2.f, ac[1], xn[mg * 2 + 0] + yn1));
                    top9_insert(tk[mg * 2 + 1], fmaf(-2.f, ac[2], xn[mg * 2 + 1] + yn0));
                    top9_insert(tk[mg * 2 + 1], fmaf(-2.f, ac[3], xn[mg * 2 + 1] + yn1));
                }
            }
#pragma unroll
            for (int i = 0; i < 64; ++i) acc[i] = 0.f;
        }

        if (++c6 == NKC) { c6 = 0; ++mi; }
        if (++b3 == NB) b3 = 0;
    }

    // ---- merge 16 per-thread lists per row (cand overlays B buffers) ----
    __syncthreads();
    const int lst = wn * 4 + (l & 3);
#pragma unroll
    for (int g = 0; g < 4; ++g) {
        int r = wm * 32 + (l >> 2) + g * 8;
#pragma unroll
        for (int j = 0; j < KK; ++j)
            cand[r * CAND_STRIDE + lst * KK + j] = tk[g][j];
    }
    __syncthreads();

    if (tid < BM) {
        float* c = &cand[tid * CAND_STRIDE];
        float* o = out + (size_t)(row0 + tid) * KK;
        const int NC = 16 * KK;   // 144
#pragma unroll 1
        for (int k = 0; k < KK; ++k) {
            float mv = c[k];
            int mi2 = k;
            for (int j = k + 1; j < NC; ++j) {
                float v = c[j];
                if (v < mv) { mv = v; mi2 = j; }
            }
            c[mi2] = c[k];
            c[k] = mv;
            o[k] = sqrtf(fmaxf(mv, 0.f));
        }
    }
}

extern "C" void kernel_launch(void* const* d_in, const int* in_sizes, int n_in,
                              void* d_out, int out_size) {
    const float* emb = (const float*)d_in[0];   // [N, D] fp32
    const float* mem = (const float*)d_in[1];   // [M, D] fp32
    float* out = (float*)d_out;                 // [N, K] fp32

    dim3 cb(32, 8);
    conv_all<<<NN / 8 + MM / 8, cb>>>(emb, mem);

    cudaFuncSetAttribute(fapm_mma, cudaFuncAttributeMaxDynamicSharedMemorySize, SMEM_BYTES);
    fapm_mma<<<NN / BM, 512, SMEM_BYTES>>>(out);
}